// round 4
// baseline (speedup 1.0000x reference)
#include <cuda_runtime.h>

// out[b] = sum_k targets[b,k] * tb[batch_indices[1],k] * scaling[k]
// targets [8192,1024] f32, temporal_bases [16384,1024] f32,
// scaling [1024] f32, batch_indices [8192] (int32 in practice), out [8192] f32.

constexpr int K = 1024;
constexpr int B = 8192;
constexpr int T = 16384;
constexpr int THREADS = 256;          // 8 warps
constexpr int WARPS_PER_BLOCK = THREADS / 32;
constexpr int K4 = K / 4;             // 256 float4

__global__ void __launch_bounds__(THREADS)
recompose_gemv_kernel(const float* __restrict__ targets,
                      const float* __restrict__ temporal_bases,
                      const float* __restrict__ scaling,
                      const void* __restrict__ batch_indices,
                      float* __restrict__ out)
{
    __shared__ float4 w4[K4];   // 4 KiB weight vector

    // Dtype-agnostic read of batch_indices[1] (int64 view valid => use it,
    // else fall back to int32 view). Clamp as last resort: no OOB ever.
    long long idx1 = ((const long long*)batch_indices)[1];
    if (idx1 < 0 || idx1 >= T)
        idx1 = (long long)(((const int*)batch_indices)[1]);
    if (idx1 < 0) idx1 = 0;
    if (idx1 >= T) idx1 = T - 1;

    const float4* tb4 = reinterpret_cast<const float4*>(
        temporal_bases + (size_t)idx1 * K);
    const float4* sc4 = reinterpret_cast<const float4*>(scaling);

    const int tid = threadIdx.x;
    {
        float4 t = tb4[tid];
        float4 s = sc4[tid];
        w4[tid] = make_float4(t.x * s.x, t.y * s.y, t.z * s.z, t.w * s.w);
    }
    __syncthreads();

    const int warp = tid >> 5;
    const int lane = tid & 31;
    const int row  = blockIdx.x * WARPS_PER_BLOCK + warp;
    if (row >= B) return;

    const float4* tg4 = reinterpret_cast<const float4*>(
        targets + (size_t)row * K);

    // Lane's weight slice: smem -> registers (once).
    float4 b0 = w4[lane +   0], b1 = w4[lane +  32];
    float4 b2 = w4[lane +  64], b3 = w4[lane +  96];
    float4 b4 = w4[lane + 128], b5 = w4[lane + 160];
    float4 b6 = w4[lane + 192], b7 = w4[lane + 224];

    // Front-batched streaming loads: 8 independent LDG.128 in flight (MLP=8).
    float4 a0 = __ldcs(&tg4[lane +   0]);
    float4 a1 = __ldcs(&tg4[lane +  32]);
    float4 a2 = __ldcs(&tg4[lane +  64]);
    float4 a3 = __ldcs(&tg4[lane +  96]);
    float4 a4 = __ldcs(&tg4[lane + 128]);
    float4 a5 = __ldcs(&tg4[lane + 160]);
    float4 a6 = __ldcs(&tg4[lane + 192]);
    float4 a7 = __ldcs(&tg4[lane + 224]);

    // 4 independent accumulator chains.
    float s0 = a0.x * b0.x + a0.y * b0.y + a0.z * b0.z + a0.w * b0.w;
    float s1 = a1.x * b1.x + a1.y * b1.y + a1.z * b1.z + a1.w * b1.w;
    float s2 = a2.x * b2.x + a2.y * b2.y + a2.z * b2.z + a2.w * b2.w;
    float s3 = a3.x * b3.x + a3.y * b3.y + a3.z * b3.z + a3.w * b3.w;
    s0 += a4.x * b4.x + a4.y * b4.y + a4.z * b4.z + a4.w * b4.w;
    s1 += a5.x * b5.x + a5.y * b5.y + a5.z * b5.z + a5.w * b5.w;
    s2 += a6.x * b6.x + a6.y * b6.y + a6.z * b6.z + a6.w * b6.w;
    s3 += a7.x * b7.x + a7.y * b7.y + a7.z * b7.z + a7.w * b7.w;

    float acc = (s0 + s1) + (s2 + s3);

    // Butterfly reduce within the warp.
#pragma unroll
    for (int off = 16; off > 0; off >>= 1)
        acc += __shfl_xor_sync(0xffffffffu, acc, off);

    if (lane == 0)
        out[row] = acc;
}

extern "C" void kernel_launch(void* const* d_in, const int* in_sizes, int n_in,
                              void* d_out, int out_size)
{
    // Identify inputs by element count — robust to metadata ordering.
    const float* targets = nullptr;
    const float* temporal_bases = nullptr;
    const float* scaling = nullptr;
    const void*  batch_indices = nullptr;

    for (int i = 0; i < n_in; ++i) {
        switch (in_sizes[i]) {
            case B * K:     targets        = (const float*)d_in[i]; break;  // 8388608
            case T * K:     temporal_bases = (const float*)d_in[i]; break;  // 16777216
            case K:         scaling        = (const float*)d_in[i]; break;  // 1024
            case B:         batch_indices  = d_in[i];               break;  // 8192
            default: break;
        }
    }

    float* out = (float*)d_out;

    dim3 grid(B / WARPS_PER_BLOCK);   // 1024 blocks
    recompose_gemv_kernel<<<grid, THREADS>>>(targets, temporal_bases,
                                             scaling, batch_indices, out);
}